// round 12
// baseline (speedup 1.0000x reference)
#include <cuda_runtime.h>
#include <cstdint>

#define T_STEPS 336
#define BATCH   4096
#define NFEAT   32
#define UN1     64
#define UN2     32
#define G1      256   // 4*UN1
#define G2      128   // 4*UN2
#define ROWS    16    // rows per CTA (2 quads of 8)
#define THREADS 256
#define CTAS    (BATCH / ROWS)   // 256 -> 2 CTAs per SM
#define RSTRIDE 128   // combined row: [x(32)|h1(64)|h2(32)]

// quad-split interleaved weights (R10/R11-proven layout), now in GMEM->L1D:
//  g_w1a[k*WK1 + up*4 ..] = { w_i(2up), w_i(2up+1), w_f(2up), w_f(2up+1) }
//  g_w1b likewise for gates g,o. k = 0..95 (stacked [W1;U1]).
#define WK1 128
#define WK2 64

__device__ float g_w1a[96 * WK1];
__device__ float g_w1b[96 * WK1];
__device__ float g_w2a[96 * WK2];
__device__ float g_w2b[96 * WK2];

typedef unsigned long long ull;

// ---------------- packed f32x2 helpers ----------------
__device__ __forceinline__ ull pack2(float a) {
    ull r; asm("mov.b64 %0, {%1, %1};" : "=l"(r) : "f"(a)); return r;
}
__device__ __forceinline__ ull pakf2(float x, float y) {
    ull r; asm("mov.b64 %0, {%1, %2};" : "=l"(r) : "f"(x), "f"(y)); return r;
}
__device__ __forceinline__ ull fma2(ull a, ull b, ull c) {
    ull d; asm("fma.rn.f32x2 %0, %1, %2, %3;" : "=l"(d) : "l"(a), "l"(b), "l"(c)); return d;
}
__device__ __forceinline__ ull add2(ull a, ull b) {
    ull d; asm("add.rn.f32x2 %0, %1, %2;" : "=l"(d) : "l"(a), "l"(b)); return d;
}
__device__ __forceinline__ float2 unpack2(ull v) {
    float2 r; asm("mov.b64 {%0, %1}, %2;" : "=f"(r.x), "=f"(r.y) : "l"(v)); return r;
}

// ---------------- fast HW math ----------------
__device__ __forceinline__ float ex2a(float x) {
    float y; asm("ex2.approx.f32 %0, %1;" : "=f"(y) : "f"(x)); return y;
}
__device__ __forceinline__ float rcpa(float x) {
    float y; asm("rcp.approx.f32 %0, %1;" : "=f"(y) : "f"(x)); return y;
}

// Full LSTM pointwise update, one row (2 units), batched reciprocals (proven):
// 10x EX2 + 2x RCP. Keras gate order i,f,c(g),o.
__device__ __forceinline__ float2 lstm_act2(float2 zi, float2 zf, float2 zg, float2 zo,
                                            float& cc0, float& cc1) {
    const float NL2E  = -1.4426950408889634f;   // -log2(e)
    const float N2L2E = -2.8853900817779268f;   // -2*log2(e)
    float ei0 = ex2a(zi.x * NL2E), ei1 = ex2a(zi.y * NL2E);
    float ef0 = ex2a(zf.x * NL2E), ef1 = ex2a(zf.y * NL2E);
    float eg0 = ex2a(fabsf(zg.x) * N2L2E), eg1 = ex2a(fabsf(zg.y) * N2L2E);
    float eo0 = ex2a(zo.x * NL2E), eo1 = ex2a(zo.y * NL2E);
    float di0 = 1.f + ei0, di1 = 1.f + ei1;
    float df0 = 1.f + ef0, df1 = 1.f + ef1;
    float dg0 = 1.f + eg0, dg1 = 1.f + eg1;
    float do0 = 1.f + eo0, do1 = 1.f + eo1;
    float p01 = di0 * di1, p23 = df0 * df1, p45 = dg0 * dg1, p67 = do0 * do1;
    float q0 = p01 * p23, q1 = p45 * p67;
    float R  = rcpa(q0 * q1);
    float iq0 = R * q1, iq1 = R * q0;
    float ip01 = iq0 * p23, ip23 = iq0 * p01;
    float ip45 = iq1 * p67, ip67 = iq1 * p45;
    float i0 = ip01 * di1, i1 = ip01 * di0;
    float f0 = ip23 * df1, f1 = ip23 * df0;
    float go0 = ip45 * dg1, go1 = ip45 * dg0;
    float o0 = ip67 * do1, o1 = ip67 * do0;
    float tg0 = copysignf((1.f - eg0) * go0, zg.x);
    float tg1 = copysignf((1.f - eg1) * go1, zg.y);
    cc0 = f0 * cc0 + i0 * tg0;
    cc1 = f1 * cc1 + i1 * tg1;
    float ec0 = ex2a(fabsf(cc0) * N2L2E), ec1 = ex2a(fabsf(cc1) * N2L2E);
    float dc0 = 1.f + ec0, dc1 = 1.f + ec1;
    float Rc = rcpa(dc0 * dc1);
    float tc0 = copysignf((1.f - ec0) * (Rc * dc1), cc0);
    float tc1 = copysignf((1.f - ec1) * (Rc * dc0), cc1);
    float2 h; h.x = o0 * tc0; h.y = o1 * tc1;
    return h;
}

// ---------------- cp.async / barrier helpers ----------------
__device__ __forceinline__ void cp16(uint32_t saddr, const float* g) {
    asm volatile("cp.async.cg.shared.global [%0], [%1], 16;" :: "r"(saddr), "l"(g));
}
__device__ __forceinline__ void cp_commit() { asm volatile("cp.async.commit_group;"); }
__device__ __forceinline__ void cp_wait0()  { asm volatile("cp.async.wait_group 0;" ::: "memory"); }
__device__ __forceinline__ void quad_bar(int id) {
    asm volatile("bar.sync %0, 128;" :: "r"(id) : "memory");
}

// 48-column panel: R rows x (2 units x 4 gates). Weights from GMEM (L1D-resident,
// gate-quad layout, 2x LDG.128 per k), inputs from SMEM via float4.
template <int R, int WK>
__device__ __forceinline__ void panelQ(ull (&acc)[R][4],
                                       const float* __restrict__ in,
                                       const float* __restrict__ wA,
                                       const float* __restrict__ wB) {
#pragma unroll 2
    for (int k = 0; k < 48; k += 4) {
        float4 a[R];
#pragma unroll
        for (int r = 0; r < R; r++) a[r] = *(const float4*)(in + r * RSTRIDE + k);
#pragma unroll
        for (int kk = 0; kk < 4; kk++) {
            uint4 ra = __ldg((const uint4*)(wA + (k + kk) * WK));
            uint4 rb = __ldg((const uint4*)(wB + (k + kk) * WK));
            ull qax = ((ull)ra.y << 32) | ra.x;
            ull qay = ((ull)ra.w << 32) | ra.z;
            ull qbx = ((ull)rb.y << 32) | rb.x;
            ull qby = ((ull)rb.w << 32) | rb.z;
#pragma unroll
            for (int r = 0; r < R; r++) {
                float av = (kk == 0) ? a[r].x : (kk == 1) ? a[r].y : (kk == 2) ? a[r].z : a[r].w;
                ull p = pack2(av);
                acc[r][0] = fma2(p, qax, acc[r][0]);
                acc[r][1] = fma2(p, qay, acc[r][1]);
                acc[r][2] = fma2(p, qbx, acc[r][2]);
                acc[r][3] = fma2(p, qby, acc[r][3]);
            }
        }
    }
}

// ---- pre-pass: reshape weights into gate-quad interleaved device arrays ----
__global__ void reshape_weights(const float* __restrict__ W1, const float* __restrict__ U1w,
                                const float* __restrict__ W2, const float* __restrict__ U2w) {
    int tid = blockIdx.x * blockDim.x + threadIdx.x;
    for (int idx = tid; idx < 96 * 32; idx += gridDim.x * blockDim.x) {
        int k = idx >> 5, u = idx & 31;
        const float* src = (k < NFEAT) ? (W1 + k * G1) : (U1w + (k - NFEAT) * G1);
        float4 qa = make_float4(src[2 * u], src[2 * u + 1],
                                src[UN1 + 2 * u], src[UN1 + 2 * u + 1]);
        float4 qb = make_float4(src[2 * UN1 + 2 * u], src[2 * UN1 + 2 * u + 1],
                                src[3 * UN1 + 2 * u], src[3 * UN1 + 2 * u + 1]);
        ((float4*)g_w1a)[k * 32 + u] = qa;
        ((float4*)g_w1b)[k * 32 + u] = qb;
    }
    for (int idx = tid; idx < 96 * 16; idx += gridDim.x * blockDim.x) {
        int k = idx >> 4, u = idx & 15;
        const float* src = (k < UN1) ? (W2 + k * G2) : (U2w + (k - UN1) * G2);
        float4 qa = make_float4(src[2 * u], src[2 * u + 1],
                                src[UN2 + 2 * u], src[UN2 + 2 * u + 1]);
        float4 qb = make_float4(src[2 * UN2 + 2 * u], src[2 * UN2 + 2 * u + 1],
                                src[3 * UN2 + 2 * u], src[3 * UN2 + 2 * u + 1]);
        ((float4*)g_w2a)[k * 16 + u] = qa;
        ((float4*)g_w2b)[k * 16 + u] = qb;
    }
}

__global__ void __launch_bounds__(THREADS, 2)
lstm_fused_kernel(const float* __restrict__ x,
                  const float* __restrict__ b1, const float* __restrict__ b2,
                  const float* __restrict__ Wv, const float* __restrict__ bv,
                  const float* __restrict__ Wo, const float* __restrict__ bo,
                  const float* __restrict__ Wd1, const float* __restrict__ bd1,
                  const float* __restrict__ Wd2, const float* __restrict__ bd2,
                  float* __restrict__ out) {
    __shared__ float smc[2 * ROWS * RSTRIDE];   // 16 KB: 2 state buffers
    const int tid = threadIdx.x;
    const int b0  = blockIdx.x * ROWS;

    // zero both state buffers
    for (int i = tid; i < 2 * ROWS * RSTRIDE; i += THREADS) smc[i] = 0.0f;

    // ---- quad mapping: 2 quads of 8 rows; quad q = warps {q, q+2, q+4, q+6} ----
    // roles: 0,1 = L1 up-halves (8-row tile); 2,3 = L2 (4-row tiles)
    const int wid  = tid >> 5;
    const int l    = tid & 31;
    const int q    = wid & 1;          // quad 0/1
    const int role = wid >> 1;         // 0..3
    const bool isL1 = (role < 2);
    const int kh   = l >> 4;           // K-half split within warp
    const int rg   = q;                            // L1 row group (8 rows)
    const int up   = (l & 15) | (role << 4);       // L1 unit pair 0..31
    const int rg2  = 2 * q + (role - 2);           // L2 row group (4 rows)
    const int up2  = l & 15;                       // L2 unit pair 0..15

    // bias -> registers (kh==0 half carries it; partner contributes 0)
    ull bq[4];
    if (isL1) {
#pragma unroll
        for (int g = 0; g < 4; g++) {
            float2 bb = (kh == 0) ? *(const float2*)(b1 + g * UN1 + 2 * up)
                                  : make_float2(0.f, 0.f);
            bq[g] = pakf2(bb.x, bb.y);
        }
    } else {
#pragma unroll
        for (int g = 0; g < 4; g++) {
            float2 bb = (kh == 0) ? *(const float2*)(b2 + g * UN2 + 2 * up2)
                                  : make_float2(0.f, 0.f);
            bq[g] = pakf2(bb.x, bb.y);
        }
    }

    float c1[4][2], c2[2][2];
#pragma unroll
    for (int r = 0; r < 4; r++) { c1[r][0] = c1[r][1] = 0.0f; }
#pragma unroll
    for (int r = 0; r < 2; r++) { c2[r][0] = c2[r][1] = 0.0f; }

    // ---- x prefetch: quad-local, movers = the quad's 2 L1 warps (64 threads) ----
    const bool xmover = isL1;
    const int m    = ((role & 1) << 5) | l;    // 0..63 within the quad's L1 pair
    const int xrow = q * 8 + (m >> 3);
    const int xq   = m & 7;
    const float* xg = x + ((size_t)(b0 + xrow) * T_STEPS) * NFEAT + xq * 4;
    uint32_t sx0 = (uint32_t)__cvta_generic_to_shared(smc + xrow * RSTRIDE + xq * 4);
    const uint32_t cbufbytes = ROWS * RSTRIDE * 4;

    __syncthreads();                    // zeroed state visible CTA-wide
    if (xmover) cp16(sx0, xg);          // x_0 -> buffer 0
    cp_commit();

    const float* wA1 = g_w1a + (kh * 48) * WK1 + up * 4;
    const float* wB1 = g_w1b + (kh * 48) * WK1 + up * 4;
    const float* wA2 = g_w2a + (kh * 48) * WK2 + up2 * 4;
    const float* wB2 = g_w2b + (kh * 48) * WK2 + up2 * 4;

    // Iter t: L1 computes step t (t<T), L2 computes step t-1 (t>=1).
    // One PER-QUAD barrier per step.
    for (int t = 0; t <= T_STEPS; ++t) {
        if (t < T_STEPS) cp_wait0();
        quad_bar(q + 1);
        if (t + 1 < T_STEPS && xmover)
            cp16(sx0 + ((t + 1) & 1) * cbufbytes, xg + (size_t)(t + 1) * NFEAT);
        cp_commit();
        const int rb = t & 1;
        const float* cin  = smc + rb * (ROWS * RSTRIDE);
        float*       cout = smc + (rb ^ 1) * (ROWS * RSTRIDE);

        if (isL1) {
            if (t < T_STEPS) {
                ull acc[8][4];
#pragma unroll
                for (int r = 0; r < 8; r++)
#pragma unroll
                    for (int g = 0; g < 4; g++) acc[r][g] = bq[g];

                panelQ<8, WK1>(acc, cin + rg * 8 * RSTRIDE + kh * 48, wA1, wB1);

#pragma unroll
                for (int r = 0; r < 8; r++)
#pragma unroll
                    for (int g = 0; g < 4; g++)
                        acc[r][g] = add2(acc[r][g], __shfl_xor_sync(0xffffffffu, acc[r][g], 16));

#pragma unroll
                for (int r = 0; r < 4; r++) {
                    float2 zi = unpack2(kh ? acc[r + 4][0] : acc[r][0]);
                    float2 zf = unpack2(kh ? acc[r + 4][1] : acc[r][1]);
                    float2 zg = unpack2(kh ? acc[r + 4][2] : acc[r][2]);
                    float2 zo = unpack2(kh ? acc[r + 4][3] : acc[r][3]);
                    float2 h = lstm_act2(zi, zf, zg, zo, c1[r][0], c1[r][1]);
                    *(float2*)(cout + (rg * 8 + kh * 4 + r) * RSTRIDE + 32 + 2 * up) = h;
                }
            }
        } else {
            if (t >= 1) {
                ull acc2[4][4];
#pragma unroll
                for (int r = 0; r < 4; r++)
#pragma unroll
                    for (int g = 0; g < 4; g++) acc2[r][g] = bq[g];

                panelQ<4, WK2>(acc2, cin + rg2 * 4 * RSTRIDE + 32 + kh * 48, wA2, wB2);

#pragma unroll
                for (int r = 0; r < 4; r++)
#pragma unroll
                    for (int g = 0; g < 4; g++)
                        acc2[r][g] = add2(acc2[r][g], __shfl_xor_sync(0xffffffffu, acc2[r][g], 16));

#pragma unroll
                for (int r = 0; r < 2; r++) {
                    float2 zi = unpack2(kh ? acc2[r + 2][0] : acc2[r][0]);
                    float2 zf = unpack2(kh ? acc2[r + 2][1] : acc2[r][1]);
                    float2 zg = unpack2(kh ? acc2[r + 2][2] : acc2[r][2]);
                    float2 zo = unpack2(kh ? acc2[r + 2][3] : acc2[r][3]);
                    float2 h = lstm_act2(zi, zf, zg, zo, c2[r][0], c2[r][1]);
                    *(float2*)(cout + (rg2 * 4 + kh * 2 + r) * RSTRIDE + 96 + 2 * up2) = h;
                }
            }
        }
    }
    __syncthreads();   // both quads done; h2 visible CTA-wide

    // final h2 = h2(T-1), written at iter t=T into buf ((T&1)^1); scratch = other buf
    const float* h2f = smc + ((T_STEPS & 1) ^ 1) * (ROWS * RSTRIDE) + 96;
    float* scr = smc + (T_STEPS & 1) * (ROWS * RSTRIDE);
    float* sv  = scr;              // 16x32
    float* so  = scr + 512;        // 16x32
    float* sd1 = scr + 1024;       // 16x64

    // ============ head: MHA(seq=1) == identity-attention -> v@Wo, then MLP ============
    for (int idx = tid; idx < ROWS * 32; idx += THREADS) {
        int r = idx >> 5, j = idx & 31;
        float s = bv[j];
        const float* h2row = h2f + r * RSTRIDE;
#pragma unroll
        for (int d = 0; d < 32; d++) s += h2row[d] * Wv[d * 32 + j];
        sv[idx] = s;
    }
    __syncthreads();
    for (int idx = tid; idx < ROWS * 32; idx += THREADS) {
        int r = idx >> 5, e = idx & 31;
        float s = bo[e];
#pragma unroll
        for (int j = 0; j < 32; j++) s += sv[r * 32 + j] * Wo[j * 32 + e];
        so[idx] = s;
    }
    __syncthreads();
    for (int idx = tid; idx < ROWS * 64; idx += THREADS) {
        int r = idx >> 6, mm = idx & 63;
        float s = bd1[mm];
#pragma unroll
        for (int e = 0; e < 32; e++) s += so[r * 32 + e] * Wd1[e * 64 + mm];
        sd1[idx] = fmaxf(s, 0.0f);
    }
    __syncthreads();
    for (int idx = tid; idx < ROWS * 24; idx += THREADS) {
        int r = idx / 24, p = idx % 24;
        float s = bd2[p];
#pragma unroll
        for (int mm = 0; mm < 64; mm++) s += sd1[r * 64 + mm] * Wd2[mm * 24 + p];
        out[(size_t)(b0 + r) * 24 + p] = s;
    }
}

extern "C" void kernel_launch(void* const* d_in, const int* in_sizes, int n_in,
                              void* d_out, int out_size) {
    const float* x   = (const float*)d_in[0];
    const float* W1  = (const float*)d_in[1];
    const float* U1w = (const float*)d_in[2];
    const float* b1  = (const float*)d_in[3];
    const float* W2  = (const float*)d_in[4];
    const float* U2w = (const float*)d_in[5];
    const float* b2  = (const float*)d_in[6];
    // d_in[7..10] = Wq, bq, Wk, bk: dead (softmax over seq-len 1 == 1)
    const float* Wv  = (const float*)d_in[11];
    const float* bv  = (const float*)d_in[12];
    const float* Wo  = (const float*)d_in[13];
    const float* bo  = (const float*)d_in[14];
    const float* Wd1 = (const float*)d_in[15];
    const float* bd1 = (const float*)d_in[16];
    const float* Wd2 = (const float*)d_in[17];
    const float* bd2 = (const float*)d_in[18];

    reshape_weights<<<12, 256>>>(W1, U1w, W2, U2w);
    lstm_fused_kernel<<<CTAS, THREADS>>>(
        x, b1, b2, Wv, bv, Wo, bo, Wd1, bd1, Wd2, bd2, (float*)d_out);
}

// round 13
// speedup vs baseline: 1.3135x; 1.3135x over previous
#include <cuda_runtime.h>
#include <cstdint>

#define T_STEPS 336
#define BATCH   4096
#define NFEAT   32
#define UN1     64
#define UN2     32
#define G1      256   // 4*UN1
#define G2      128   // 4*UN2
#define ROWS    32
#define THREADS 512
#define CTAS    (BATCH / ROWS)   // 128
#define RSTRIDE 128   // combined row: [x(32)|h1(64)|h2(32)]
// row swizzle: spreads 4-row groups across banks (rg lanes -> banks 0,4,..,28)
#define ROWBASE(r) ((r) * RSTRIDE + ((((r) >> 2) & 7) << 2))
#define BUFSZ (ROWS * RSTRIDE + 32)   // 4128 floats per state buffer

// quad-split interleaved weights (R10/R11-proven):
//  W1A[k][up] = float4{ w_i(2up), w_i(2up+1), w_f(2up), w_f(2up+1) }, k = 0..95
//  W1B likewise gates g,o. Row stride WK floats.
#define WK1 128
#define WK2 64

// ---- shared memory layout (float offsets) ----
#define OFF_W1A 0
#define OFF_W1B (OFF_W1A + 96 * WK1)            // 12288
#define OFF_W2A (OFF_W1B + 96 * WK1)            // 24576
#define OFF_W2B (OFF_W2A + 96 * WK2)            // 30720
#define OFF_C   (OFF_W2B + 96 * WK2)            // 36864
#define SMEM_FLOATS (OFF_C + 2 * BUFSZ)         // 45120 -> 180480 bytes

typedef unsigned long long ull;

// ---------------- packed f32x2 helpers ----------------
__device__ __forceinline__ ull pack2(float a) {
    ull r; asm("mov.b64 %0, {%1, %1};" : "=l"(r) : "f"(a)); return r;
}
__device__ __forceinline__ ull pakf2(float x, float y) {
    ull r; asm("mov.b64 %0, {%1, %2};" : "=l"(r) : "f"(x), "f"(y)); return r;
}
__device__ __forceinline__ ull fma2(ull a, ull b, ull c) {
    ull d; asm("fma.rn.f32x2 %0, %1, %2, %3;" : "=l"(d) : "l"(a), "l"(b), "l"(c)); return d;
}
__device__ __forceinline__ float2 unpack2(ull v) {
    float2 r; asm("mov.b64 {%0, %1}, %2;" : "=f"(r.x), "=f"(r.y) : "l"(v)); return r;
}

// ---------------- fast HW math ----------------
__device__ __forceinline__ float ex2a(float x) {
    float y; asm("ex2.approx.f32 %0, %1;" : "=f"(y) : "f"(x)); return y;
}
__device__ __forceinline__ float rcpa(float x) {
    float y; asm("rcp.approx.f32 %0, %1;" : "=f"(y) : "f"(x)); return y;
}

// Full LSTM pointwise update, one row (2 units), batched reciprocals (proven):
// 10x EX2 + 2x RCP. Keras gate order i,f,c(g),o.
__device__ __forceinline__ float2 lstm_act2(float2 zi, float2 zf, float2 zg, float2 zo,
                                            float& cc0, float& cc1) {
    const float NL2E  = -1.4426950408889634f;   // -log2(e)
    const float N2L2E = -2.8853900817779268f;   // -2*log2(e)
    float ei0 = ex2a(zi.x * NL2E), ei1 = ex2a(zi.y * NL2E);
    float ef0 = ex2a(zf.x * NL2E), ef1 = ex2a(zf.y * NL2E);
    float eg0 = ex2a(fabsf(zg.x) * N2L2E), eg1 = ex2a(fabsf(zg.y) * N2L2E);
    float eo0 = ex2a(zo.x * NL2E), eo1 = ex2a(zo.y * NL2E);
    float di0 = 1.f + ei0, di1 = 1.f + ei1;
    float df0 = 1.f + ef0, df1 = 1.f + ef1;
    float dg0 = 1.f + eg0, dg1 = 1.f + eg1;
    float do0 = 1.f + eo0, do1 = 1.f + eo1;
    float p01 = di0 * di1, p23 = df0 * df1, p45 = dg0 * dg1, p67 = do0 * do1;
    float q0 = p01 * p23, q1 = p45 * p67;
    float R  = rcpa(q0 * q1);
    float iq0 = R * q1, iq1 = R * q0;
    float ip01 = iq0 * p23, ip23 = iq0 * p01;
    float ip45 = iq1 * p67, ip67 = iq1 * p45;
    float i0 = ip01 * di1, i1 = ip01 * di0;
    float f0 = ip23 * df1, f1 = ip23 * df0;
    float go0 = ip45 * dg1, go1 = ip45 * dg0;
    float o0 = ip67 * do1, o1 = ip67 * do0;
    float tg0 = copysignf((1.f - eg0) * go0, zg.x);
    float tg1 = copysignf((1.f - eg1) * go1, zg.y);
    cc0 = f0 * cc0 + i0 * tg0;
    cc1 = f1 * cc1 + i1 * tg1;
    float ec0 = ex2a(fabsf(cc0) * N2L2E), ec1 = ex2a(fabsf(cc1) * N2L2E);
    float dc0 = 1.f + ec0, dc1 = 1.f + ec1;
    float Rc = rcpa(dc0 * dc1);
    float tc0 = copysignf((1.f - ec0) * (Rc * dc1), cc0);
    float tc1 = copysignf((1.f - ec1) * (Rc * dc0), cc1);
    float2 h; h.x = o0 * tc0; h.y = o1 * tc1;
    return h;
}

// ---------------- cp.async helpers ----------------
__device__ __forceinline__ void cp16(uint32_t saddr, const float* g) {
    asm volatile("cp.async.cg.shared.global [%0], [%1], 16;" :: "r"(saddr), "l"(g));
}
__device__ __forceinline__ void cp_commit() { asm volatile("cp.async.commit_group;"); }
__device__ __forceinline__ void cp_wait0()  { asm volatile("cp.async.wait_group 0;" ::: "memory"); }

// Full-K (96) panel: R rows x (2 units x 4 gates). Weights read ONCE per CTA:
// thread owns its unit-pair slice for all K. 2x LDS.128 per k, float4 inputs.
template <int R, int WK>
__device__ __forceinline__ void panelFull(ull (&acc)[R][4], const float* in,
                                          const float* wA, const float* wB) {
#pragma unroll 2
    for (int k = 0; k < 96; k += 4) {
        float4 a[R];
#pragma unroll
        for (int r = 0; r < R; r++) a[r] = *(const float4*)(in + r * RSTRIDE + k);
#pragma unroll
        for (int kk = 0; kk < 4; kk++) {
            ulonglong2 qa = *(const ulonglong2*)(wA + (k + kk) * WK);
            ulonglong2 qb = *(const ulonglong2*)(wB + (k + kk) * WK);
#pragma unroll
            for (int r = 0; r < R; r++) {
                float av = (kk == 0) ? a[r].x : (kk == 1) ? a[r].y : (kk == 2) ? a[r].z : a[r].w;
                ull p = pack2(av);
                acc[r][0] = fma2(p, qa.x, acc[r][0]);
                acc[r][1] = fma2(p, qa.y, acc[r][1]);
                acc[r][2] = fma2(p, qb.x, acc[r][2]);
                acc[r][3] = fma2(p, qb.y, acc[r][3]);
            }
        }
    }
}

__global__ void __launch_bounds__(THREADS, 1)
lstm_fused_kernel(const float* __restrict__ x,
                  const float* __restrict__ W1, const float* __restrict__ U1w, const float* __restrict__ b1,
                  const float* __restrict__ W2, const float* __restrict__ U2w, const float* __restrict__ b2,
                  const float* __restrict__ Wv, const float* __restrict__ bv,
                  const float* __restrict__ Wo, const float* __restrict__ bo,
                  const float* __restrict__ Wd1, const float* __restrict__ bd1,
                  const float* __restrict__ Wd2, const float* __restrict__ bd2,
                  float* __restrict__ out) {
    extern __shared__ float sm[];
    const int tid = threadIdx.x;
    const int b0  = blockIdx.x * ROWS;

    // ---- stage weights into quad-split interleaved SMEM arrays (R11-proven) ----
    for (int idx = tid; idx < 96 * 32; idx += THREADS) {
        int k = idx >> 5, u = idx & 31;
        const float* src = (k < NFEAT) ? (W1 + k * G1) : (U1w + (k - NFEAT) * G1);
        float4 qa = make_float4(src[2 * u], src[2 * u + 1],
                                src[UN1 + 2 * u], src[UN1 + 2 * u + 1]);
        float4 qb = make_float4(src[2 * UN1 + 2 * u], src[2 * UN1 + 2 * u + 1],
                                src[3 * UN1 + 2 * u], src[3 * UN1 + 2 * u + 1]);
        ((float4*)(sm + OFF_W1A))[k * 32 + u] = qa;
        ((float4*)(sm + OFF_W1B))[k * 32 + u] = qb;
    }
    for (int idx = tid; idx < 96 * 16; idx += THREADS) {
        int k = idx >> 4, u = idx & 15;
        const float* src = (k < UN1) ? (W2 + k * G2) : (U2w + (k - UN1) * G2);
        float4 qa = make_float4(src[2 * u], src[2 * u + 1],
                                src[UN2 + 2 * u], src[UN2 + 2 * u + 1]);
        float4 qb = make_float4(src[2 * UN2 + 2 * u], src[2 * UN2 + 2 * u + 1],
                                src[3 * UN2 + 2 * u], src[3 * UN2 + 2 * u + 1]);
        ((float4*)(sm + OFF_W2A))[k * 16 + u] = qa;
        ((float4*)(sm + OFF_W2B))[k * 16 + u] = qb;
    }
    for (int i = tid; i < 2 * BUFSZ; i += THREADS) sm[OFF_C + i] = 0.0f;

    // ---- unit-sliced mapping: each warp owns gate-columns for ALL 32 rows ----
    // warps 0-7  = L1: warp w -> ups w*4..w*4+3; thread = 4 rows x 1 up x 4 gates
    // warps 8-15 = L2: warp w -> ups (w-8)*2..+1; thread = 2 rows x 1 up x 4 gates
    const int wid = tid >> 5;
    const int l   = tid & 31;
    const bool isL1 = (wid < 8);
    const int up  = (wid << 2) | (l & 3);      // L1 unit pair 0..31
    const int rg  = l >> 2;                    // L1 row group: rows rg*4..+3
    const int up2 = ((wid - 8) << 1) | (l & 1);// L2 unit pair 0..15
    const int rg2 = l >> 1;                    // L2 row group: rows rg2*2..+1

    // full bias in registers for every lane (no K-split)
    ull bq[4];
    if (isL1) {
#pragma unroll
        for (int g = 0; g < 4; g++) {
            float2 bb = *(const float2*)(b1 + g * UN1 + 2 * up);
            bq[g] = pakf2(bb.x, bb.y);
        }
    } else {
#pragma unroll
        for (int g = 0; g < 4; g++) {
            float2 bb = *(const float2*)(b2 + g * UN2 + 2 * up2);
            bq[g] = pakf2(bb.x, bb.y);
        }
    }

    float c1[4][2], c2[2][2];
#pragma unroll
    for (int r = 0; r < 4; r++) { c1[r][0] = c1[r][1] = 0.0f; }
#pragma unroll
    for (int r = 0; r < 2; r++) { c2[r][0] = c2[r][1] = 0.0f; }

    // ---- x prefetch: movers = warps 8-11 (L2, lighter); 2 float4 per thread ----
    const bool xmover = (wid >= 8 && wid < 12);
    const int m    = ((wid - 8) << 5) | l;     // 0..127
    const int mrow = m >> 2;                   // 0..31
    const int mq   = (m & 3) << 1;             // 0,2,4,6
    const float* xg = x + ((size_t)(b0 + mrow) * T_STEPS) * NFEAT + mq * 4;
    uint32_t sx0 = (uint32_t)__cvta_generic_to_shared(sm + OFF_C + ROWBASE(mrow) + mq * 4);
    const uint32_t cbufbytes = BUFSZ * 4;

    __syncthreads();                    // staging visible before cp.async writes x
    if (xmover) { cp16(sx0, xg); cp16(sx0 + 16, xg + 4); cp_commit(); }

    const float* wA1 = sm + OFF_W1A + up * 4;
    const float* wB1 = sm + OFF_W1B + up * 4;
    const float* wA2 = sm + OFF_W2A + up2 * 4;
    const float* wB2 = sm + OFF_W2B + up2 * 4;

    // Iter t: L1 computes step t (t<T), L2 computes step t-1 (t>=1).
    // Single CTA-wide barrier per step (columns produced by all warps).
    for (int t = 0; t <= T_STEPS; ++t) {
        if (xmover && t < T_STEPS) cp_wait0();
        __syncthreads();
        if (xmover && t + 1 < T_STEPS) {
            uint32_t dst = sx0 + ((t + 1) & 1) * cbufbytes;
            const float* src = xg + (size_t)(t + 1) * NFEAT;
            cp16(dst, src); cp16(dst + 16, src + 4);
            cp_commit();
        }
        const int rb = t & 1;
        const float* cin  = sm + OFF_C + rb * BUFSZ;
        float*       cout = sm + OFF_C + (rb ^ 1) * BUFSZ;

        if (isL1) {
            if (t < T_STEPS) {
                ull acc[4][4];
#pragma unroll
                for (int r = 0; r < 4; r++)
#pragma unroll
                    for (int g = 0; g < 4; g++) acc[r][g] = bq[g];

                // gate K-rows [x|h1] = cin cols 0..95, full K per thread
                panelFull<4, WK1>(acc, cin + ROWBASE(rg * 4), wA1, wB1);

#pragma unroll
                for (int r = 0; r < 4; r++) {
                    float2 h = lstm_act2(unpack2(acc[r][0]), unpack2(acc[r][1]),
                                         unpack2(acc[r][2]), unpack2(acc[r][3]),
                                         c1[r][0], c1[r][1]);
                    *(float2*)(cout + ROWBASE(rg * 4 + r) + 32 + 2 * up) = h;   // h1(t)
                }
            }
        } else {
            if (t >= 1) {
                ull acc2[2][4];
#pragma unroll
                for (int r = 0; r < 2; r++)
#pragma unroll
                    for (int g = 0; g < 4; g++) acc2[r][g] = bq[g];

                // gate K-rows [h1(t-1)|h2(t-2)] = cin cols 32..127, full K
                panelFull<2, WK2>(acc2, cin + ROWBASE(rg2 * 2) + 32, wA2, wB2);

#pragma unroll
                for (int r = 0; r < 2; r++) {
                    float2 h = lstm_act2(unpack2(acc2[r][0]), unpack2(acc2[r][1]),
                                         unpack2(acc2[r][2]), unpack2(acc2[r][3]),
                                         c2[r][0], c2[r][1]);
                    *(float2*)(cout + ROWBASE(rg2 * 2 + r) + 96 + 2 * up2) = h; // h2(t-1)
                }
            }
        }
    }
    __syncthreads();

    // final h2 = h2(T-1), written at iter t=T into buf ((T&1)^1)
    const float* h2f = sm + OFF_C + ((T_STEPS & 1) ^ 1) * BUFSZ;

    // ============ head: MHA(seq=1) == identity-attention -> v@Wo, then MLP ============
    float* sv  = sm;            // scratch in dead weight region
    float* so  = sm + 1024;
    float* sd1 = sm + 2048;
    for (int idx = tid; idx < ROWS * 32; idx += THREADS) {
        int r = idx >> 5, j = idx & 31;
        float s = bv[j];
        const float* h2row = h2f + ROWBASE(r) + 96;
#pragma unroll
        for (int d = 0; d < 32; d++) s += h2row[d] * Wv[d * 32 + j];
        sv[idx] = s;
    }
    __syncthreads();
    for (int idx = tid; idx < ROWS * 32; idx += THREADS) {
        int r = idx >> 5, e = idx & 31;
        float s = bo[e];
#pragma unroll
        for (int j = 0; j < 32; j++) s += sv[r * 32 + j] * Wo[j * 32 + e];
        so[idx] = s;
    }
    __syncthreads();
    for (int idx = tid; idx < ROWS * 64; idx += THREADS) {
        int r = idx >> 6, mm = idx & 63;
        float s = bd1[mm];
#pragma unroll
        for (int e = 0; e < 32; e++) s += so[r * 32 + e] * Wd1[e * 64 + mm];
        sd1[idx] = fmaxf(s, 0.0f);
    }
    __syncthreads();
    for (int idx = tid; idx < ROWS * 24; idx += THREADS) {
        int r = idx / 24, p = idx % 24;
        float s = bd2[p];
#pragma unroll
        for (int mm = 0; mm < 64; mm++) s += sd1[r * 64 + mm] * Wd2[mm * 24 + p];
        out[(size_t)(b0 + r) * 24 + p] = s;
    }
}

extern "C" void kernel_launch(void* const* d_in, const int* in_sizes, int n_in,
                              void* d_out, int out_size) {
    const float* x   = (const float*)d_in[0];
    const float* W1  = (const float*)d_in[1];
    const float* U1w = (const float*)d_in[2];
    const float* b1  = (const float*)d_in[3];
    const float* W2  = (const float*)d_in[4];
    const float* U2w = (const float*)d_in[5];
    const float* b2  = (const float*)d_in[6];
    // d_in[7..10] = Wq, bq, Wk, bk: dead (softmax over seq-len 1 == 1)
    const float* Wv  = (const float*)d_in[11];
    const float* bv  = (const float*)d_in[12];
    const float* Wo  = (const float*)d_in[13];
    const float* bo  = (const float*)d_in[14];
    const float* Wd1 = (const float*)d_in[15];
    const float* bd1 = (const float*)d_in[16];
    const float* Wd2 = (const float*)d_in[17];
    const float* bd2 = (const float*)d_in[18];

    size_t smem = SMEM_FLOATS * sizeof(float);   // 180480 B
    cudaFuncSetAttribute(lstm_fused_kernel,
                         cudaFuncAttributeMaxDynamicSharedMemorySize, (int)smem);
    lstm_fused_kernel<<<CTAS, THREADS, smem>>>(
        x, W1, U1w, b1, W2, U2w, b2, Wv, bv, Wo, bo, Wd1, bd1, Wd2, bd2,
        (float*)d_out);
}